// round 7
// baseline (speedup 1.0000x reference)
#include <cuda_runtime.h>
#include <cstddef>
#include <cstdint>

// ---------------- problem constants ----------------
constexpr int BWIN = 4096;
constexpr int NTOK = 64;
constexpr int CDIM = 256;
constexpr int HEADS = 8;
constexpr int DHEAD = 32;
constexpr int MROWS = BWIN * NTOK;          // 262144
constexpr float SCALE = 0.1767766952966369f; // 32^-0.5

// ---------------- scratch ----------------
__device__ float g_q[BWIN * HEADS * NTOK * DHEAD];
__device__ float g_k[BWIN * HEADS * NTOK * DHEAD];
__device__ float g_v[BWIN * HEADS * NTOK * DHEAD];
__device__ float g_o[MROWS * CDIM];     // permuted tf32 (A of proj GEMM)
__device__ float g_xt[MROWS * CDIM];    // permuted tf32 x
__device__ float g_wt[1024 * CDIM];     // permuted tf32 weights: [0,256)=Wq, [256,768)=Wkv, [768,1024)=Wp

// ---------------- helpers ----------------
__device__ __forceinline__ float to_tf32(float x) {
    unsigned r;
    asm("cvt.rna.tf32.f32 %0, %1;" : "=r"(r) : "f"(x));
    return __uint_as_float(r);
}
__device__ __forceinline__ unsigned f2u(float x) { return __float_as_uint(x); }

__device__ __forceinline__ void mma_tf32(float* c, unsigned a0, unsigned a1,
                                         unsigned a2, unsigned a3,
                                         unsigned b0, unsigned b1) {
    asm volatile(
        "mma.sync.aligned.m16n8k8.row.col.f32.tf32.tf32.f32 "
        "{%0,%1,%2,%3}, {%4,%5,%6,%7}, {%8,%9}, {%0,%1,%2,%3};"
        : "+f"(c[0]), "+f"(c[1]), "+f"(c[2]), "+f"(c[3])
        : "r"(a0), "r"(a1), "r"(a2), "r"(a3), "r"(b0), "r"(b1));
}

__device__ __forceinline__ void cp16(uint32_t dst, const void* src) {
    asm volatile("cp.async.cg.shared.global [%0], [%1], 16;" :: "r"(dst), "l"(src) : "memory");
}
__device__ __forceinline__ void cp_commit() {
    asm volatile("cp.async.commit_group;" ::: "memory");
}
__device__ __forceinline__ void cp_wait2() {
    asm volatile("cp.async.wait_group 2;" ::: "memory");
}

// ---------------- permute + tf32 round ----------------
// dst[row*256 + 16g + 4c + q] = tf32(src[row*256 + 16g + 4q + c])
__global__ void __launch_bounds__(256) permute_tf32(
    const float* __restrict__ src, float* __restrict__ dst, int ngroups)
{
    int g = blockIdx.x * 256 + threadIdx.x;
    if (g >= ngroups) return;
    const float4* s = (const float4*)src + (size_t)g * 4;
    float4 v0 = s[0], v1 = s[1], v2 = s[2], v3 = s[3];
    float4* d = (float4*)dst + (size_t)g * 4;
    d[0] = make_float4(to_tf32(v0.x), to_tf32(v1.x), to_tf32(v2.x), to_tf32(v3.x));
    d[1] = make_float4(to_tf32(v0.y), to_tf32(v1.y), to_tf32(v2.y), to_tf32(v3.y));
    d[2] = make_float4(to_tf32(v0.z), to_tf32(v1.z), to_tf32(v2.z), to_tf32(v3.z));
    d[3] = make_float4(to_tf32(v0.w), to_tf32(v1.w), to_tf32(v2.w), to_tf32(v3.w));
}

// ---------------- TF32 tensor GEMM, cp.async pipelined ----------------
// out[m,c] = A[m,:] . W[c,:] + b[c];  A,W pre-permuted tf32.
// BM=128, BN=64, BK=16, 4 stages; 8 warps (4x2), warp tile 32x32.
// MODE 0: A=g_xt, W rows 0..767 of g_wt; cols->g_q(scaled)/g_k/g_v scatter.
// MODE 1: A=g_o,  W rows 768..1023 of g_wt -> outP.
template <int MODE>
__global__ void __launch_bounds__(256, 2) mma_gemm(
    const float* __restrict__ b0v, const float* __restrict__ b1v,
    float* __restrict__ outP)
{
    constexpr int STAGES = 4;
    __shared__ float4 As4[STAGES][128 * 4];
    __shared__ float4 Bs4[STAGES][64 * 4];

    const float* A = (MODE == 0) ? g_xt : g_o;
    const int c0 = blockIdx.x * 64;                // c-tile fastest -> A cached in L2
    const int m0 = blockIdx.y * 128;
    const float* Wsrc = g_wt + (MODE == 0 ? 0 : 768 * CDIM);

    const int t = threadIdx.x;
    const int wid = t >> 5, lane = t & 31;
    const int wm = wid & 3, wn = wid >> 2;
    const int gid = lane >> 2, tig = lane & 3;
    const int mrow = wm * 32, ncol = wn * 32;

    float c[2][4][4];
#pragma unroll
    for (int mt = 0; mt < 2; mt++)
#pragma unroll
        for (int nt = 0; nt < 4; nt++)
#pragma unroll
            for (int i = 0; i < 4; i++) c[mt][nt][i] = 0.f;

    // ---- cp.async per-thread mapping ----
    const int arow = t >> 2;       // 0..63
    const int ac = t & 3;          // logical chunk
    const int apc  = ac ^ ((arow >> 1) & 3);
    const int arowB = arow + 64;
    const int apcB = ac ^ ((arowB >> 1) & 3);

    const uint32_t dA0 = (uint32_t)__cvta_generic_to_shared(&As4[0][arow * 4 + apc]);
    const uint32_t dA1 = (uint32_t)__cvta_generic_to_shared(&As4[0][arowB * 4 + apcB]);
    const uint32_t dB  = (uint32_t)__cvta_generic_to_shared(&Bs4[0][arow * 4 + apc]);
    constexpr uint32_t ASTRIDE = 128 * 4 * 16;
    constexpr uint32_t BSTRIDE = 64 * 4 * 16;

    const float* srcA0 = A + (size_t)(m0 + arow) * CDIM + ac * 4;
    const float* srcA1 = A + (size_t)(m0 + arow + 64) * CDIM + ac * 4;
    const float* srcB  = Wsrc + (size_t)(c0 + arow) * CDIM + ac * 4;

    auto issue = [&](int kt, int s) {
        cp16(dA0 + s * ASTRIDE, srcA0 + kt * 16);
        cp16(dA1 + s * ASTRIDE, srcA1 + kt * 16);
        cp16(dB  + s * BSTRIDE, srcB  + kt * 16);
    };

    // ---- fragment load indices (float4 units) ----
    int aIdx[2][2], bIdx[4];
#pragma unroll
    for (int mt = 0; mt < 2; mt++) {
        int r0 = mrow + mt * 16 + gid;
        int r1 = r0 + 8;
        aIdx[mt][0] = r0 * 4 + (tig ^ ((r0 >> 1) & 3));
        aIdx[mt][1] = r1 * 4 + (tig ^ ((r1 >> 1) & 3));
    }
#pragma unroll
    for (int nt = 0; nt < 4; nt++) {
        int nb = ncol + nt * 8 + gid;
        bIdx[nt] = nb * 4 + (tig ^ ((nb >> 1) & 3));
    }

    // ---- prologue: stages 0..2 ----
#pragma unroll
    for (int s = 0; s < STAGES - 1; s++) {
        issue(s, s);
        cp_commit();
    }

#pragma unroll
    for (int kt = 0; kt < 16; kt++) {
        const int buf = kt & 3;
        cp_wait2();
        __syncthreads();

        {
            const float4* as = As4[buf];
            const float4* bs = Bs4[buf];
            float4 a4[2][2], b4[4];
#pragma unroll
            for (int mt = 0; mt < 2; mt++) {
                a4[mt][0] = as[aIdx[mt][0]];
                a4[mt][1] = as[aIdx[mt][1]];
            }
#pragma unroll
            for (int nt = 0; nt < 4; nt++) b4[nt] = bs[bIdx[nt]];

#pragma unroll
            for (int mt = 0; mt < 2; mt++)
#pragma unroll
                for (int nt = 0; nt < 4; nt++)
                    mma_tf32(c[mt][nt],
                             f2u(a4[mt][0].x), f2u(a4[mt][1].x),
                             f2u(a4[mt][0].y), f2u(a4[mt][1].y),
                             f2u(b4[nt].x),    f2u(b4[nt].y));
#pragma unroll
            for (int mt = 0; mt < 2; mt++)
#pragma unroll
                for (int nt = 0; nt < 4; nt++)
                    mma_tf32(c[mt][nt],
                             f2u(a4[mt][0].z), f2u(a4[mt][1].z),
                             f2u(a4[mt][0].w), f2u(a4[mt][1].w),
                             f2u(b4[nt].z),    f2u(b4[nt].w));
        }

        if (kt + STAGES - 1 < 16) issue(kt + STAGES - 1, (kt + STAGES - 1) & 3);
        cp_commit();
    }

    // ---------------- epilogue ----------------
#pragma unroll
    for (int mt = 0; mt < 2; mt++) {
#pragma unroll
        for (int nt = 0; nt < 4; nt++) {
            int clocal = ncol + nt * 8 + 2 * tig;
            int cg = c0 + clocal;
            float bias0, bias1;
            if (MODE == 1) { bias0 = b0v[cg]; bias1 = b0v[cg + 1]; }
            else if (cg < 256) { bias0 = b0v[cg]; bias1 = b0v[cg + 1]; }
            else { bias0 = b1v[cg - 256]; bias1 = b1v[cg - 255]; }
#pragma unroll
            for (int rr = 0; rr < 2; rr++) {
                int row = m0 + mrow + mt * 16 + gid + rr * 8;
                float v0 = c[mt][nt][rr * 2 + 0] + bias0;
                float v1 = c[mt][nt][rr * 2 + 1] + bias1;
                if (MODE == 1) {
                    float2* p = (float2*)(outP + (size_t)row * CDIM + cg);
                    *p = make_float2(v0, v1);
                } else {
                    int cc = cg;
                    int b = row >> 6, n = row & 63;
                    float* base;
                    if (cc < 256) { base = g_q; v0 *= SCALE; v1 *= SCALE; }
                    else if (cc < 512) { base = g_k; cc -= 256; }
                    else { base = g_v; cc -= 512; }
                    int hh = cc >> 5, dd = cc & 31;
                    float2* p = (float2*)(base + (((size_t)(b * 8 + hh)) * 64 + n) * 32 + dd);
                    *p = make_float2(v0, v1);
                }
            }
        }
    }
}

// ---------------- fused attention per (window, head) ----------------
__global__ void __launch_bounds__(256) attn_kernel(
    const float* __restrict__ mask,
    const float* __restrict__ bias_table)
{
    const int bh = blockIdx.x;
    const int b  = bh >> 3;
    const int h  = bh & 7;

    __shared__ float qs_t[32 * 64];
    __shared__ float ks_t[32 * 64];
    __shared__ float vs[64 * 32];
    __shared__ float S[64 * 65];
    __shared__ float rowmax[64];
    __shared__ float rowinv[64];

    const int t = threadIdx.x;
    const float* qg = g_q + (size_t)bh * 2048;
    const float* kg = g_k + (size_t)bh * 2048;
    const float* vg = g_v + (size_t)bh * 2048;

#pragma unroll
    for (int it = 0; it < 2; it++) {
        int e = (t + it * 256) * 4;
        int n = e >> 5;
        int d = e & 31;
        float4 vq = *(const float4*)&qg[e];
        float4 vk = *(const float4*)&kg[e];
        float4 vv = *(const float4*)&vg[e];
        qs_t[(d + 0) * 64 + n] = vq.x;
        qs_t[(d + 1) * 64 + n] = vq.y;
        qs_t[(d + 2) * 64 + n] = vq.z;
        qs_t[(d + 3) * 64 + n] = vq.w;
        ks_t[(d + 0) * 64 + n] = vk.x;
        ks_t[(d + 1) * 64 + n] = vk.y;
        ks_t[(d + 2) * 64 + n] = vk.z;
        ks_t[(d + 3) * 64 + n] = vk.w;
        *(float4*)&vs[e] = vv;
    }
    __syncthreads();

    const int i0 = (t >> 4) << 2;
    const int j0 = (t & 15) << 2;
    float s[4][4];
#pragma unroll
    for (int i = 0; i < 4; i++)
#pragma unroll
        for (int j = 0; j < 4; j++) s[i][j] = 0.f;

#pragma unroll
    for (int d = 0; d < 32; d++) {
        float qr[4], kr[4];
        *(float4*)qr = *(const float4*)&qs_t[d * 64 + i0];
        *(float4*)kr = *(const float4*)&ks_t[d * 64 + j0];
#pragma unroll
        for (int i = 0; i < 4; i++)
#pragma unroll
            for (int j = 0; j < 4; j++)
                s[i][j] = fmaf(qr[i], kr[j], s[i][j]);
    }

    const int w = b & 1023;
    const float* mrow = mask + (size_t)w * 4096;
#pragma unroll
    for (int i = 0; i < 4; i++) {
        int ii = i0 + i;
        int ih = ii >> 3, iw = ii & 7;
#pragma unroll
        for (int j = 0; j < 4; j++) {
            int jj = j0 + j;
            int jh = jj >> 3, jw = jj & 7;
            int ridx = (ih - jh + 7) * 15 + (iw - jw + 7);
            S[ii * 65 + jj] = s[i][j] + bias_table[ridx * 8 + h] + mrow[ii * 64 + jj];
        }
    }
    __syncthreads();

    if (t < 64) {
        float mx = S[t * 65];
        for (int j = 1; j < 64; j++) mx = fmaxf(mx, S[t * 65 + j]);
        rowmax[t] = mx;
    }
    __syncthreads();

#pragma unroll
    for (int i = 0; i < 4; i++) {
        float mx = rowmax[i0 + i];
#pragma unroll
        for (int j = 0; j < 4; j++) {
            int idx = (i0 + i) * 65 + (j0 + j);
            S[idx] = __expf(S[idx] - mx);
        }
    }
    __syncthreads();

    if (t < 64) {
        float ssum = 0.f;
        for (int j = 0; j < 64; j++) ssum += S[t * 65 + j];
        rowinv[t] = 1.0f / ssum;
    }
    __syncthreads();

    const int oi = t >> 2;
    const int d0 = (t & 3) << 3;
    float o[8];
#pragma unroll
    for (int dd = 0; dd < 8; dd++) o[dd] = 0.f;

    for (int j = 0; j < 64; j++) {
        float p = S[oi * 65 + j];
        float4 va = *(const float4*)&vs[j * 32 + d0];
        float4 vb = *(const float4*)&vs[j * 32 + d0 + 4];
        o[0] = fmaf(p, va.x, o[0]);
        o[1] = fmaf(p, va.y, o[1]);
        o[2] = fmaf(p, va.z, o[2]);
        o[3] = fmaf(p, va.w, o[3]);
        o[4] = fmaf(p, vb.x, o[4]);
        o[5] = fmaf(p, vb.y, o[5]);
        o[6] = fmaf(p, vb.z, o[6]);
        o[7] = fmaf(p, vb.w, o[7]);
    }
    float inv = rowinv[oi];
    // store permuted + tf32-rounded (A operand of proj GEMM)
    size_t rowoff = ((size_t)(b * 64 + oi)) * CDIM;
    int colbase = h * 32 + d0;
#pragma unroll
    for (int dd = 0; dd < 8; dd++) {
        int col = colbase + dd;
        int p = (col & ~15) | ((col & 3) << 2) | ((col >> 2) & 3);
        g_o[rowoff + p] = to_tf32(o[dd] * inv);
    }
}

// ---------------- launch ----------------
extern "C" void kernel_launch(void* const* d_in, const int* in_sizes, int n_in,
                              void* d_out, int out_size)
{
    const float* x          = (const float*)d_in[0];
    const float* mask       = (const float*)d_in[1];
    const float* Wq         = (const float*)d_in[2];
    const float* bq         = (const float*)d_in[3];
    const float* Wkv        = (const float*)d_in[4];
    const float* bkv        = (const float*)d_in[5];
    const float* bias_table = (const float*)d_in[6];
    const float* Wp         = (const float*)d_in[7];
    const float* bp         = (const float*)d_in[8];
    float* out = (float*)d_out;

    float* wt;
    cudaGetSymbolAddress((void**)&wt, g_wt);
    float* xt;
    cudaGetSymbolAddress((void**)&xt, g_xt);

    // permute + tf32 round operands
    permute_tf32<<<(MROWS * 16 + 255) / 256, 256>>>(x, xt, MROWS * 16);
    permute_tf32<<<(256 * 16 + 255) / 256, 256>>>(Wq, wt, 256 * 16);
    permute_tf32<<<(512 * 16 + 255) / 256, 256>>>(Wkv, wt + 256 * CDIM, 512 * 16);
    permute_tf32<<<(256 * 16 + 255) / 256, 256>>>(Wp, wt + 768 * CDIM, 256 * 16);

    mma_gemm<0><<<dim3(12, MROWS / 128), 256>>>(bq, bkv, nullptr);
    attn_kernel<<<BWIN * HEADS, 256>>>(mask, bias_table);
    mma_gemm<1><<<dim3(4, MROWS / 128), 256>>>(bp, nullptr, out);
}

// round 8
// speedup vs baseline: 1.5055x; 1.5055x over previous
#include <cuda_runtime.h>
#include <cstddef>
#include <cstdint>

// ---------------- problem constants ----------------
constexpr int BWIN = 4096;
constexpr int NTOK = 64;
constexpr int CDIM = 256;
constexpr int HEADS = 8;
constexpr int DHEAD = 32;
constexpr int MROWS = BWIN * NTOK;          // 262144
constexpr float SCALE = 0.1767766952966369f; // 32^-0.5

// ---------------- scratch ----------------
// q/k: [bh][n][32] k-permuted tf32.  v: [bh][d][64] n-permuted tf32 (transposed).
__device__ float g_q[BWIN * HEADS * NTOK * DHEAD];
__device__ float g_k[BWIN * HEADS * NTOK * DHEAD];
__device__ float g_v[BWIN * HEADS * NTOK * DHEAD];
__device__ float g_o[MROWS * CDIM];     // permuted tf32 (A of proj GEMM)
__device__ float g_xt[MROWS * CDIM];    // permuted tf32 x
__device__ float g_wt[1024 * CDIM];     // permuted tf32 weights
__device__ float g_bias8[HEADS * 64 * 64]; // expanded relative-position bias

// ---------------- helpers ----------------
__device__ __forceinline__ float to_tf32(float x) {
    unsigned r;
    asm("cvt.rna.tf32.f32 %0, %1;" : "=r"(r) : "f"(x));
    return __uint_as_float(r);
}
__device__ __forceinline__ unsigned f2u(float x) { return __float_as_uint(x); }

__device__ __forceinline__ void mma_tf32(float* c, unsigned a0, unsigned a1,
                                         unsigned a2, unsigned a3,
                                         unsigned b0, unsigned b1) {
    asm volatile(
        "mma.sync.aligned.m16n8k8.row.col.f32.tf32.tf32.f32 "
        "{%0,%1,%2,%3}, {%4,%5,%6,%7}, {%8,%9}, {%0,%1,%2,%3};"
        : "+f"(c[0]), "+f"(c[1]), "+f"(c[2]), "+f"(c[3])
        : "r"(a0), "r"(a1), "r"(a2), "r"(a3), "r"(b0), "r"(b1));
}

__device__ __forceinline__ void cp16(uint32_t dst, const void* src) {
    asm volatile("cp.async.cg.shared.global [%0], [%1], 16;" :: "r"(dst), "l"(src) : "memory");
}
__device__ __forceinline__ void cp_commit() {
    asm volatile("cp.async.commit_group;" ::: "memory");
}
__device__ __forceinline__ void cp_wait2() {
    asm volatile("cp.async.wait_group 2;" ::: "memory");
}

// ---------------- permute + tf32 round ----------------
__global__ void __launch_bounds__(256) permute_tf32(
    const float* __restrict__ src, float* __restrict__ dst, int ngroups)
{
    int g = blockIdx.x * 256 + threadIdx.x;
    if (g >= ngroups) return;
    const float4* s = (const float4*)src + (size_t)g * 4;
    float4 v0 = s[0], v1 = s[1], v2 = s[2], v3 = s[3];
    float4* d = (float4*)dst + (size_t)g * 4;
    d[0] = make_float4(to_tf32(v0.x), to_tf32(v1.x), to_tf32(v2.x), to_tf32(v3.x));
    d[1] = make_float4(to_tf32(v0.y), to_tf32(v1.y), to_tf32(v2.y), to_tf32(v3.y));
    d[2] = make_float4(to_tf32(v0.z), to_tf32(v1.z), to_tf32(v2.z), to_tf32(v3.z));
    d[3] = make_float4(to_tf32(v0.w), to_tf32(v1.w), to_tf32(v2.w), to_tf32(v3.w));
}

// ---------------- expand relative-position bias to [h][i][j] ----------------
__global__ void __launch_bounds__(256) bias8_kernel(const float* __restrict__ bias_table)
{
    int idx = blockIdx.x * 256 + threadIdx.x;   // 0..32767
    int h = idx >> 12;
    int ij = idx & 4095;
    int i = ij >> 6, j = ij & 63;
    int ih = i >> 3, iw = i & 7, jh = j >> 3, jw = j & 7;
    int ridx = (ih - jh + 7) * 15 + (iw - jw + 7);
    g_bias8[idx] = bias_table[ridx * 8 + h];
}

// ---------------- TF32 tensor GEMM, cp.async pipelined ----------------
template <int MODE>
__global__ void __launch_bounds__(256, 2) mma_gemm(
    const float* __restrict__ b0v, const float* __restrict__ b1v,
    float* __restrict__ outP)
{
    constexpr int STAGES = 4;
    __shared__ float4 As4[STAGES][128 * 4];
    __shared__ float4 Bs4[STAGES][64 * 4];

    const float* A = (MODE == 0) ? g_xt : g_o;
    const int c0 = blockIdx.x * 64;
    const int m0 = blockIdx.y * 128;
    const float* Wsrc = g_wt + (MODE == 0 ? 0 : 768 * CDIM);

    const int t = threadIdx.x;
    const int wid = t >> 5, lane = t & 31;
    const int wm = wid & 3, wn = wid >> 2;
    const int gid = lane >> 2, tig = lane & 3;
    const int mrow = wm * 32, ncol = wn * 32;

    float c[2][4][4];
#pragma unroll
    for (int mt = 0; mt < 2; mt++)
#pragma unroll
        for (int nt = 0; nt < 4; nt++)
#pragma unroll
            for (int i = 0; i < 4; i++) c[mt][nt][i] = 0.f;

    const int arow = t >> 2;
    const int ac = t & 3;
    const int apc  = ac ^ ((arow >> 1) & 3);
    const int arowB = arow + 64;
    const int apcB = ac ^ ((arowB >> 1) & 3);

    const uint32_t dA0 = (uint32_t)__cvta_generic_to_shared(&As4[0][arow * 4 + apc]);
    const uint32_t dA1 = (uint32_t)__cvta_generic_to_shared(&As4[0][arowB * 4 + apcB]);
    const uint32_t dB  = (uint32_t)__cvta_generic_to_shared(&Bs4[0][arow * 4 + apc]);
    constexpr uint32_t ASTRIDE = 128 * 4 * 16;
    constexpr uint32_t BSTRIDE = 64 * 4 * 16;

    const float* srcA0 = A + (size_t)(m0 + arow) * CDIM + ac * 4;
    const float* srcA1 = A + (size_t)(m0 + arow + 64) * CDIM + ac * 4;
    const float* srcB  = Wsrc + (size_t)(c0 + arow) * CDIM + ac * 4;

    auto issue = [&](int kt, int s) {
        cp16(dA0 + s * ASTRIDE, srcA0 + kt * 16);
        cp16(dA1 + s * ASTRIDE, srcA1 + kt * 16);
        cp16(dB  + s * BSTRIDE, srcB  + kt * 16);
    };

    int aIdx[2][2], bIdx[4];
#pragma unroll
    for (int mt = 0; mt < 2; mt++) {
        int r0 = mrow + mt * 16 + gid;
        int r1 = r0 + 8;
        aIdx[mt][0] = r0 * 4 + (tig ^ ((r0 >> 1) & 3));
        aIdx[mt][1] = r1 * 4 + (tig ^ ((r1 >> 1) & 3));
    }
#pragma unroll
    for (int nt = 0; nt < 4; nt++) {
        int nb = ncol + nt * 8 + gid;
        bIdx[nt] = nb * 4 + (tig ^ ((nb >> 1) & 3));
    }

#pragma unroll
    for (int s = 0; s < STAGES - 1; s++) {
        issue(s, s);
        cp_commit();
    }

#pragma unroll
    for (int kt = 0; kt < 16; kt++) {
        const int buf = kt & 3;
        cp_wait2();
        __syncthreads();

        {
            const float4* as = As4[buf];
            const float4* bs = Bs4[buf];
            float4 a4[2][2], b4[4];
#pragma unroll
            for (int mt = 0; mt < 2; mt++) {
                a4[mt][0] = as[aIdx[mt][0]];
                a4[mt][1] = as[aIdx[mt][1]];
            }
#pragma unroll
            for (int nt = 0; nt < 4; nt++) b4[nt] = bs[bIdx[nt]];

#pragma unroll
            for (int mt = 0; mt < 2; mt++)
#pragma unroll
                for (int nt = 0; nt < 4; nt++)
                    mma_tf32(c[mt][nt],
                             f2u(a4[mt][0].x), f2u(a4[mt][1].x),
                             f2u(a4[mt][0].y), f2u(a4[mt][1].y),
                             f2u(b4[nt].x),    f2u(b4[nt].y));
#pragma unroll
            for (int mt = 0; mt < 2; mt++)
#pragma unroll
                for (int nt = 0; nt < 4; nt++)
                    mma_tf32(c[mt][nt],
                             f2u(a4[mt][0].z), f2u(a4[mt][1].z),
                             f2u(a4[mt][0].w), f2u(a4[mt][1].w),
                             f2u(b4[nt].z),    f2u(b4[nt].w));
        }

        if (kt + STAGES - 1 < 16) issue(kt + STAGES - 1, (kt + STAGES - 1) & 3);
        cp_commit();
    }

    // ---------------- epilogue ----------------
#pragma unroll
    for (int mt = 0; mt < 2; mt++) {
#pragma unroll
        for (int nt = 0; nt < 4; nt++) {
            int clocal = ncol + nt * 8 + 2 * tig;
            int cg = c0 + clocal;
            float bias0, bias1;
            if (MODE == 1) { bias0 = b0v[cg]; bias1 = b0v[cg + 1]; }
            else if (cg < 256) { bias0 = b0v[cg]; bias1 = b0v[cg + 1]; }
            else { bias0 = b1v[cg - 256]; bias1 = b1v[cg - 255]; }
#pragma unroll
            for (int rr = 0; rr < 2; rr++) {
                int row = m0 + mrow + mt * 16 + gid + rr * 8;
                float v0 = c[mt][nt][rr * 2 + 0] + bias0;
                float v1 = c[mt][nt][rr * 2 + 1] + bias1;
                if (MODE == 1) {
                    float2* p = (float2*)(outP + (size_t)row * CDIM + cg);
                    *p = make_float2(v0, v1);
                } else {
                    int cc = cg;
                    int b = row >> 6, n = row & 63;
                    if (cc < 512) {
                        // q/k: [bh][n][32], k-permuted within 16-groups
                        float* base;
                        if (cc < 256) { base = g_q; v0 *= SCALE; v1 *= SCALE; }
                        else { base = g_k; cc -= 256; }
                        int hh = cc >> 5, dd = cc & 31;
                        int pp = (dd & 16) + ((dd & 3) << 2) + ((dd >> 2) & 3);
                        float* p = base + ((size_t)(b * 8 + hh)) * 2048 + n * 32;
                        p[pp] = to_tf32(v0);
                        p[pp + 4] = to_tf32(v1);   // dd even -> dd+1 maps to pp+4
                    } else {
                        // v: transposed [bh][d][64], n-permuted within 16-groups
                        cc -= 512;
                        int hh = cc >> 5, dd = cc & 31;
                        int pn = (n & ~15) + ((n & 3) << 2) + ((n >> 2) & 3);
                        float* p = g_v + ((size_t)(b * 8 + hh)) * 2048 + dd * 64 + pn;
                        p[0] = to_tf32(v0);
                        p[64] = to_tf32(v1);
                    }
                }
            }
        }
    }
}

// ---------------- tensor-core attention per (window, head) ----------------
// 128 threads, 4 warps; warp w owns Q rows [16w, 16w+16). No shared memory.
__global__ void __launch_bounds__(128) attn_kernel(const float* __restrict__ mask)
{
    const int bh = blockIdx.x;
    const int b  = bh >> 3;
    const int h  = bh & 7;
    const int w  = b & 1023;

    const int t = threadIdx.x;
    const int wid = t >> 5, lane = t & 31;
    const int gid = lane >> 2, tig = lane & 3;
    const int i0 = wid * 16 + gid;   // row for c slots 0,1
    const int i1 = i0 + 8;           // row for c slots 2,3

    const float* qg = g_q + (size_t)bh * 2048;
    const float* kg = g_k + (size_t)bh * 2048;
    const float* vg = g_v + (size_t)bh * 2048;

    // ---- Q A-fragments (direct global float4, permuted layout) ----
    float4 qa00 = *(const float4*)(qg + i0 * 32 + tig * 4);        // rows i0, k-group 0
    float4 qa01 = *(const float4*)(qg + i0 * 32 + 16 + tig * 4);   // k-group 1
    float4 qa10 = *(const float4*)(qg + i1 * 32 + tig * 4);
    float4 qa11 = *(const float4*)(qg + i1 * 32 + 16 + tig * 4);

    // ---- S = Q.K^T : 8 n-tiles x 4 k-steps ----
    float c[8][4];
#pragma unroll
    for (int nt = 0; nt < 8; nt++) {
        c[nt][0] = c[nt][1] = c[nt][2] = c[nt][3] = 0.f;
        const float* krow = kg + (8 * nt + gid) * 32;
        float4 kb0 = *(const float4*)(krow + tig * 4);
        float4 kb1 = *(const float4*)(krow + 16 + tig * 4);
        mma_tf32(c[nt], f2u(qa00.x), f2u(qa10.x), f2u(qa00.y), f2u(qa10.y), f2u(kb0.x), f2u(kb0.y));
        mma_tf32(c[nt], f2u(qa00.z), f2u(qa10.z), f2u(qa00.w), f2u(qa10.w), f2u(kb0.z), f2u(kb0.w));
        mma_tf32(c[nt], f2u(qa01.x), f2u(qa11.x), f2u(qa01.y), f2u(qa11.y), f2u(kb1.x), f2u(kb1.y));
        mma_tf32(c[nt], f2u(qa01.z), f2u(qa11.z), f2u(qa01.w), f2u(qa11.w), f2u(kb1.z), f2u(kb1.w));
    }

    // ---- add mask + bias, find row maxes ----
    const float* mrow = mask + (size_t)w * 4096;
    const float* brow = g_bias8 + h * 4096;
    float mx0 = -1e30f, mx1 = -1e30f;
#pragma unroll
    for (int nt = 0; nt < 8; nt++) {
        int coff = nt * 8 + 2 * tig;
        float2 m0 = *(const float2*)(mrow + i0 * 64 + coff);
        float2 b0 = *(const float2*)(brow + i0 * 64 + coff);
        float2 m1 = *(const float2*)(mrow + i1 * 64 + coff);
        float2 b1 = *(const float2*)(brow + i1 * 64 + coff);
        c[nt][0] += m0.x + b0.x;
        c[nt][1] += m0.y + b0.y;
        c[nt][2] += m1.x + b1.x;
        c[nt][3] += m1.y + b1.y;
        mx0 = fmaxf(mx0, fmaxf(c[nt][0], c[nt][1]));
        mx1 = fmaxf(mx1, fmaxf(c[nt][2], c[nt][3]));
    }
    mx0 = fmaxf(mx0, __shfl_xor_sync(~0u, mx0, 1));
    mx0 = fmaxf(mx0, __shfl_xor_sync(~0u, mx0, 2));
    mx1 = fmaxf(mx1, __shfl_xor_sync(~0u, mx1, 1));
    mx1 = fmaxf(mx1, __shfl_xor_sync(~0u, mx1, 2));

    // ---- exp + row sums ----
    float s0 = 0.f, s1 = 0.f;
#pragma unroll
    for (int nt = 0; nt < 8; nt++) {
        c[nt][0] = __expf(c[nt][0] - mx0);
        c[nt][1] = __expf(c[nt][1] - mx0);
        c[nt][2] = __expf(c[nt][2] - mx1);
        c[nt][3] = __expf(c[nt][3] - mx1);
        s0 += c[nt][0] + c[nt][1];
        s1 += c[nt][2] + c[nt][3];
    }
    s0 += __shfl_xor_sync(~0u, s0, 1);
    s0 += __shfl_xor_sync(~0u, s0, 2);
    s1 += __shfl_xor_sync(~0u, s1, 1);
    s1 += __shfl_xor_sync(~0u, s1, 2);
    float r0 = 1.0f / s0, r1 = 1.0f / s1;
#pragma unroll
    for (int nt = 0; nt < 8; nt++) {
        c[nt][0] = to_tf32(c[nt][0] * r0);
        c[nt][1] = to_tf32(c[nt][1] * r0);
        c[nt][2] = to_tf32(c[nt][2] * r1);
        c[nt][3] = to_tf32(c[nt][3] * r1);
    }

    // ---- convert P (C-layout) -> A-fragments via shuffles ----
    unsigned a[8][4];
    const int src1 = (gid << 2) + (tig >> 1);
    const int src2 = src1 + 2;
    const bool odd = (tig & 1);
#pragma unroll
    for (int kt = 0; kt < 8; kt++) {
        float p0 = __shfl_sync(~0u, c[kt][0], src1);
        float p1 = __shfl_sync(~0u, c[kt][1], src1);
        float p2 = __shfl_sync(~0u, c[kt][2], src1);
        float p3 = __shfl_sync(~0u, c[kt][3], src1);
        float q0 = __shfl_sync(~0u, c[kt][0], src2);
        float q1 = __shfl_sync(~0u, c[kt][1], src2);
        float q2 = __shfl_sync(~0u, c[kt][2], src2);
        float q3 = __shfl_sync(~0u, c[kt][3], src2);
        a[kt][0] = f2u(odd ? p1 : p0);
        a[kt][1] = f2u(odd ? p3 : p2);
        a[kt][2] = f2u(odd ? q1 : q0);
        a[kt][3] = f2u(odd ? q3 : q2);
    }

    // ---- O = P.V : 4 n-tiles (dv) x 8 k-steps ----
    float co[4][4];
#pragma unroll
    for (int nt = 0; nt < 4; nt++)
        co[nt][0] = co[nt][1] = co[nt][2] = co[nt][3] = 0.f;

#pragma unroll
    for (int g = 0; g < 4; g++) {       // j-groups of 16
        float4 vb[4];
#pragma unroll
        for (int nt = 0; nt < 4; nt++)
            vb[nt] = *(const float4*)(vg + (8 * nt + gid) * 64 + g * 16 + tig * 4);
        int kt0 = 2 * g;
#pragma unroll
        for (int nt = 0; nt < 4; nt++) {
            mma_tf32(co[nt], a[kt0][0], a[kt0][1], a[kt0][2], a[kt0][3],
                     f2u(vb[nt].x), f2u(vb[nt].y));
            mma_tf32(co[nt], a[kt0 + 1][0], a[kt0 + 1][1], a[kt0 + 1][2], a[kt0 + 1][3],
                     f2u(vb[nt].z), f2u(vb[nt].w));
        }
    }

    // ---- store O into g_o (permuted tf32) ----
    size_t orow0 = ((size_t)(b * 64 + i0)) * CDIM;
    size_t orow1 = ((size_t)(b * 64 + i1)) * CDIM;
#pragma unroll
    for (int nt = 0; nt < 4; nt++) {
        int col = h * 32 + nt * 8 + 2 * tig;     // even
        int p = (col & ~15) | ((col & 3) << 2) | ((col >> 2) & 3);
        g_o[orow0 + p]     = to_tf32(co[nt][0]);
        g_o[orow0 + p + 4] = to_tf32(co[nt][1]);
        g_o[orow1 + p]     = to_tf32(co[nt][2]);
        g_o[orow1 + p + 4] = to_tf32(co[nt][3]);
    }
}

// ---------------- launch ----------------
extern "C" void kernel_launch(void* const* d_in, const int* in_sizes, int n_in,
                              void* d_out, int out_size)
{
    const float* x          = (const float*)d_in[0];
    const float* mask       = (const float*)d_in[1];
    const float* Wq         = (const float*)d_in[2];
    const float* bq         = (const float*)d_in[3];
    const float* Wkv        = (const float*)d_in[4];
    const float* bkv        = (const float*)d_in[5];
    const float* bias_table = (const float*)d_in[6];
    const float* Wp         = (const float*)d_in[7];
    const float* bp         = (const float*)d_in[8];
    float* out = (float*)d_out;

    float* wt;
    cudaGetSymbolAddress((void**)&wt, g_wt);
    float* xt;
    cudaGetSymbolAddress((void**)&xt, g_xt);

    permute_tf32<<<(MROWS * 16 + 255) / 256, 256>>>(x, xt, MROWS * 16);
    permute_tf32<<<(256 * 16 + 255) / 256, 256>>>(Wq, wt, 256 * 16);
    permute_tf32<<<(512 * 16 + 255) / 256, 256>>>(Wkv, wt + 256 * CDIM, 512 * 16);
    permute_tf32<<<(256 * 16 + 255) / 256, 256>>>(Wp, wt + 768 * CDIM, 256 * 16);
    bias8_kernel<<<128, 256>>>(bias_table);

    mma_gemm<0><<<dim3(12, MROWS / 128), 256>>>(bq, bkv, nullptr);
    attn_kernel<<<BWIN * HEADS, 128>>>(mask);
    mma_gemm<1><<<dim3(4, MROWS / 128), 256>>>(bp, nullptr, out);
}

// round 10
// speedup vs baseline: 1.5449x; 1.0262x over previous
#include <cuda_runtime.h>
#include <cstddef>
#include <cstdint>

// ---------------- problem constants ----------------
constexpr int BWIN = 4096;
constexpr int NTOK = 64;
constexpr int CDIM = 256;
constexpr int HEADS = 8;
constexpr int MROWS = BWIN * NTOK;          // 262144
constexpr float SCALE = 0.1767766952966369f; // 32^-0.5

// ---------------- scratch ----------------
// q/k: [bh][n][32] k-permuted tf32.  v: [bh][d][64] n-permuted tf32 (transposed).
__device__ float g_q[BWIN * HEADS * NTOK * 32];
__device__ float g_k[BWIN * HEADS * NTOK * 32];
__device__ float g_v[BWIN * HEADS * NTOK * 32];
__device__ float g_o[MROWS * CDIM];     // permuted tf32 (A of proj GEMM)
__device__ float g_xt[MROWS * CDIM];    // permuted tf32 x
__device__ float g_wt[1024 * CDIM];     // permuted tf32 weights
__device__ float g_bias8[HEADS * 64 * 64];

// ---------------- helpers ----------------
__device__ __forceinline__ float to_tf32(float x) {
    unsigned r;
    asm("cvt.rna.tf32.f32 %0, %1;" : "=r"(r) : "f"(x));
    return __uint_as_float(r);
}
__device__ __forceinline__ unsigned f2u(float x) { return __float_as_uint(x); }

__device__ __forceinline__ void mma_tf32(float* c, unsigned a0, unsigned a1,
                                         unsigned a2, unsigned a3,
                                         unsigned b0, unsigned b1) {
    asm volatile(
        "mma.sync.aligned.m16n8k8.row.col.f32.tf32.tf32.f32 "
        "{%0,%1,%2,%3}, {%4,%5,%6,%7}, {%8,%9}, {%0,%1,%2,%3};"
        : "+f"(c[0]), "+f"(c[1]), "+f"(c[2]), "+f"(c[3])
        : "r"(a0), "r"(a1), "r"(a2), "r"(a3), "r"(b0), "r"(b1));
}

__device__ __forceinline__ void cp16(uint32_t dst, const void* src) {
    asm volatile("cp.async.cg.shared.global [%0], [%1], 16;" :: "r"(dst), "l"(src) : "memory");
}
__device__ __forceinline__ void cp_commit() {
    asm volatile("cp.async.commit_group;" ::: "memory");
}
template <int N>
__device__ __forceinline__ void cp_wait() {
    asm volatile("cp.async.wait_group %0;" :: "n"(N) : "memory");
}

// ---------------- permute + tf32 round ----------------
__global__ void __launch_bounds__(256) permute_tf32(
    const float* __restrict__ src, float* __restrict__ dst, int ngroups)
{
    int g = blockIdx.x * 256 + threadIdx.x;
    if (g >= ngroups) return;
    const float4* s = (const float4*)src + (size_t)g * 4;
    float4 v0 = s[0], v1 = s[1], v2 = s[2], v3 = s[3];
    float4* d = (float4*)dst + (size_t)g * 4;
    d[0] = make_float4(to_tf32(v0.x), to_tf32(v1.x), to_tf32(v2.x), to_tf32(v3.x));
    d[1] = make_float4(to_tf32(v0.y), to_tf32(v1.y), to_tf32(v2.y), to_tf32(v3.y));
    d[2] = make_float4(to_tf32(v0.z), to_tf32(v1.z), to_tf32(v2.z), to_tf32(v3.z));
    d[3] = make_float4(to_tf32(v0.w), to_tf32(v1.w), to_tf32(v2.w), to_tf32(v3.w));
}

// ---------------- expand relative-position bias to [h][i][j] ----------------
__global__ void __launch_bounds__(256) bias8_kernel(const float* __restrict__ bias_table)
{
    int idx = blockIdx.x * 256 + threadIdx.x;
    int h = idx >> 12;
    int ij = idx & 4095;
    int i = ij >> 6, j = ij & 63;
    int ih = i >> 3, iw = i & 7, jh = j >> 3, jw = j & 7;
    int ridx = (ih - jh + 7) * 15 + (iw - jw + 7);
    g_bias8[idx] = bias_table[ridx * 8 + h];
}

// ---------------- TF32 tensor GEMM, cp.async 3-stage ----------------
// CTA tile 128x128xK256; 8 warps (4m x 2n), warp tile 32x64 (2x8 m16n8k8).
// MODE 0: A=g_xt, W rows 0..767 of g_wt; cols->g_q(scaled)/g_k/g_v scatter.
// MODE 1: A=g_o,  W rows 768..1023 of g_wt -> outP.
template <int MODE>
__global__ void __launch_bounds__(256, 2) mma_gemm(
    const float* __restrict__ b0v, const float* __restrict__ b1v,
    float* __restrict__ outP)
{
    constexpr int STAGES = 3;
    __shared__ float4 As4[STAGES][128 * 4];
    __shared__ float4 Bs4[STAGES][128 * 4];

    const float* A = (MODE == 0) ? g_xt : g_o;
    const int c0 = blockIdx.x * 128;
    const int m0 = blockIdx.y * 128;
    const float* Wsrc = g_wt + (MODE == 0 ? 0 : 768 * CDIM);

    const int t = threadIdx.x;
    const int wid = t >> 5, lane = t & 31;
    const int wm = wid & 3, wn = wid >> 2;
    const int gid = lane >> 2, tig = lane & 3;
    const int mrow = wm * 32, ncol = wn * 64;

    float c[2][8][4];
#pragma unroll
    for (int mt = 0; mt < 2; mt++)
#pragma unroll
        for (int nt = 0; nt < 8; nt++)
#pragma unroll
            for (int i = 0; i < 4; i++) c[mt][nt][i] = 0.f;

    // ---- cp.async mapping: rows t>>2 and t>>2+64 of both tiles ----
    const int arow = t >> 2;
    const int ac = t & 3;
    const int apc  = ac ^ ((arow >> 1) & 3);
    const int arowB = arow + 64;
    const int apcB = ac ^ ((arowB >> 1) & 3);

    const uint32_t dA0 = (uint32_t)__cvta_generic_to_shared(&As4[0][arow * 4 + apc]);
    const uint32_t dA1 = (uint32_t)__cvta_generic_to_shared(&As4[0][arowB * 4 + apcB]);
    const uint32_t dB0 = (uint32_t)__cvta_generic_to_shared(&Bs4[0][arow * 4 + apc]);
    const uint32_t dB1 = (uint32_t)__cvta_generic_to_shared(&Bs4[0][arowB * 4 + apcB]);
    constexpr uint32_t STRIDE = 128 * 4 * 16;   // 8 KB per stage

    const float* srcA0 = A + (size_t)(m0 + arow) * CDIM + ac * 4;
    const float* srcA1 = A + (size_t)(m0 + arow + 64) * CDIM + ac * 4;
    const float* srcB0 = Wsrc + (size_t)(c0 + arow) * CDIM + ac * 4;
    const float* srcB1 = Wsrc + (size_t)(c0 + arow + 64) * CDIM + ac * 4;

    auto issue = [&](int kt, int s) {
        cp16(dA0 + s * STRIDE, srcA0 + kt * 16);
        cp16(dA1 + s * STRIDE, srcA1 + kt * 16);
        cp16(dB0 + s * STRIDE, srcB0 + kt * 16);
        cp16(dB1 + s * STRIDE, srcB1 + kt * 16);
        cp_commit();
    };

    // ---- fragment load indices (float4 units) ----
    int aIdx[2][2], bIdx[8];
#pragma unroll
    for (int mt = 0; mt < 2; mt++) {
        int r0 = mrow + mt * 16 + gid;
        int r1 = r0 + 8;
        aIdx[mt][0] = r0 * 4 + (tig ^ ((r0 >> 1) & 3));
        aIdx[mt][1] = r1 * 4 + (tig ^ ((r1 >> 1) & 3));
    }
#pragma unroll
    for (int nt = 0; nt < 8; nt++) {
        int nb = ncol + nt * 8 + gid;
        bIdx[nt] = nb * 4 + (tig ^ ((nb >> 1) & 3));
    }

    issue(0, 0);
    issue(1, 1);

#pragma unroll
    for (int kt = 0; kt < 16; kt++) {
        const int buf = kt % 3;
        cp_wait<1>();
        __syncthreads();

        {
            const float4* as = As4[buf];
            const float4* bs = Bs4[buf];
            float4 a4[2][2];
#pragma unroll
            for (int mt = 0; mt < 2; mt++) {
                a4[mt][0] = as[aIdx[mt][0]];
                a4[mt][1] = as[aIdx[mt][1]];
            }
#pragma unroll
            for (int half = 0; half < 2; half++) {
                float4 b4[4];
#pragma unroll
                for (int j = 0; j < 4; j++) b4[j] = bs[bIdx[half * 4 + j]];
#pragma unroll
                for (int mt = 0; mt < 2; mt++)
#pragma unroll
                    for (int j = 0; j < 4; j++) {
                        float* cc = c[mt][half * 4 + j];
                        mma_tf32(cc,
                                 f2u(a4[mt][0].x), f2u(a4[mt][1].x),
                                 f2u(a4[mt][0].y), f2u(a4[mt][1].y),
                                 f2u(b4[j].x),     f2u(b4[j].y));
                        mma_tf32(cc,
                                 f2u(a4[mt][0].z), f2u(a4[mt][1].z),
                                 f2u(a4[mt][0].w), f2u(a4[mt][1].w),
                                 f2u(b4[j].z),     f2u(b4[j].w));
                    }
            }
        }
        __syncthreads();
        if (kt + 2 < 16) issue(kt + 2, (kt + 2) % 3);
    }

    // ---------------- epilogue ----------------
#pragma unroll
    for (int mt = 0; mt < 2; mt++) {
#pragma unroll
        for (int nt = 0; nt < 8; nt++) {
            int clocal = ncol + nt * 8 + 2 * tig;
            int cg = c0 + clocal;
            float bias0, bias1;
            if (MODE == 1) { bias0 = b0v[cg]; bias1 = b0v[cg + 1]; }
            else if (cg < 256) { bias0 = b0v[cg]; bias1 = b0v[cg + 1]; }
            else { bias0 = b1v[cg - 256]; bias1 = b1v[cg - 255]; }
#pragma unroll
            for (int rr = 0; rr < 2; rr++) {
                int row = m0 + mrow + mt * 16 + gid + rr * 8;
                float v0 = c[mt][nt][rr * 2 + 0] + bias0;
                float v1 = c[mt][nt][rr * 2 + 1] + bias1;
                if (MODE == 1) {
                    float2* p = (float2*)(outP + (size_t)row * CDIM + cg);
                    *p = make_float2(v0, v1);
                } else {
                    int cc = cg;
                    int b = row >> 6, n = row & 63;
                    if (cc < 512) {
                        float* base;
                        if (cc < 256) { base = g_q; v0 *= SCALE; v1 *= SCALE; }
                        else { base = g_k; cc -= 256; }
                        int hh = cc >> 5, dd = cc & 31;
                        int pp = (dd & 16) + ((dd & 3) << 2) + ((dd >> 2) & 3);
                        float* p = base + ((size_t)(b * 8 + hh)) * 2048 + n * 32;
                        p[pp] = to_tf32(v0);
                        p[pp + 4] = to_tf32(v1);
                    } else {
                        cc -= 512;
                        int hh = cc >> 5, dd = cc & 31;
                        int pn = (n & ~15) + ((n & 3) << 2) + ((n >> 2) & 3);
                        float* p = g_v + ((size_t)(b * 8 + hh)) * 2048 + dd * 64 + pn;
                        p[0] = to_tf32(v0);
                        p[64] = to_tf32(v1);
                    }
                }
            }
        }
    }
}

// ---------------- tensor-core attention per (window, head) ----------------
__global__ void __launch_bounds__(128) attn_kernel(const float* __restrict__ mask)
{
    const int bh = blockIdx.x;
    const int b  = bh >> 3;
    const int h  = bh & 7;
    const int w  = b & 1023;

    const int t = threadIdx.x;
    const int wid = t >> 5, lane = t & 31;
    const int gid = lane >> 2, tig = lane & 3;
    const int i0 = wid * 16 + gid;
    const int i1 = i0 + 8;

    const float* qg = g_q + (size_t)bh * 2048;
    const float* kg = g_k + (size_t)bh * 2048;
    const float* vg = g_v + (size_t)bh * 2048;

    float4 qa00 = *(const float4*)(qg + i0 * 32 + tig * 4);
    float4 qa01 = *(const float4*)(qg + i0 * 32 + 16 + tig * 4);
    float4 qa10 = *(const float4*)(qg + i1 * 32 + tig * 4);
    float4 qa11 = *(const float4*)(qg + i1 * 32 + 16 + tig * 4);

    float c[8][4];
#pragma unroll
    for (int nt = 0; nt < 8; nt++) {
        c[nt][0] = c[nt][1] = c[nt][2] = c[nt][3] = 0.f;
        const float* krow = kg + (8 * nt + gid) * 32;
        float4 kb0 = *(const float4*)(krow + tig * 4);
        float4 kb1 = *(const float4*)(krow + 16 + tig * 4);
        mma_tf32(c[nt], f2u(qa00.x), f2u(qa10.x), f2u(qa00.y), f2u(qa10.y), f2u(kb0.x), f2u(kb0.y));
        mma_tf32(c[nt], f2u(qa00.z), f2u(qa10.z), f2u(qa00.w), f2u(qa10.w), f2u(kb0.z), f2u(kb0.w));
        mma_tf32(c[nt], f2u(qa01.x), f2u(qa11.x), f2u(qa01.y), f2u(qa11.y), f2u(kb1.x), f2u(kb1.y));
        mma_tf32(c[nt], f2u(qa01.z), f2u(qa11.z), f2u(qa01.w), f2u(qa11.w), f2u(kb1.z), f2u(kb1.w));
    }

    const float* mrow = mask + (size_t)w * 4096;
    const float* brow = g_bias8 + h * 4096;
    float mx0 = -1e30f, mx1 = -1e30f;
#pragma unroll
    for (int nt = 0; nt < 8; nt++) {
        int coff = nt * 8 + 2 * tig;
        float2 m0 = *(const float2*)(mrow + i0 * 64 + coff);
        float2 b0 = *(const float2*)(brow + i0 * 64 + coff);
        float2 m1 = *(const float2*)(mrow + i1 * 64 + coff);
        float2 b1 = *(const float2*)(brow + i1 * 64 + coff);
        c[nt][0] += m0.x + b0.x;
        c[nt][1] += m0.y + b0.y;
        c[nt][2] += m1.x + b1.x;
        c[nt][3] += m1.y + b1.y;
        mx0 = fmaxf(mx0, fmaxf(c[nt][0], c[nt][1]));
        mx1 = fmaxf(mx1, fmaxf(c[nt][2], c[nt][3]));
    }
    mx0 = fmaxf(mx0, __shfl_xor_sync(~0u, mx0, 1));
    mx0 = fmaxf(mx0, __shfl_xor_sync(~0u, mx0, 2));
    mx1 = fmaxf(mx1, __shfl_xor_sync(~0u, mx1, 1));
    mx1 = fmaxf(mx1, __shfl_xor_sync(~0u, mx1, 2));

    float s0 = 0.f, s1 = 0.f;
#pragma unroll
    for (int nt = 0; nt < 8; nt++) {
        c[nt][0] = __expf(c[nt][0] - mx0);
        c[nt][1] = __expf(c[nt][1] - mx0);
        c[nt][2] = __expf(c[nt][2] - mx1);
        c[nt][3] = __expf(c[nt][3] - mx1);
        s0 += c[nt][0] + c[nt][1];
        s1 += c[nt][2] + c[nt][3];
    }
    s0 += __shfl_xor_sync(~0u, s0, 1);
    s0 += __shfl_xor_sync(~0u, s0, 2);
    s1 += __shfl_xor_sync(~0u, s1, 1);
    s1 += __shfl_xor_sync(~0u, s1, 2);
    float r0 = 1.0f / s0, r1 = 1.0f / s1;
#pragma unroll
    for (int nt = 0; nt < 8; nt++) {
        c[nt][0] = to_tf32(c[nt][0] * r0);
        c[nt][1] = to_tf32(c[nt][1] * r0);
        c[nt][2] = to_tf32(c[nt][2] * r1);
        c[nt][3] = to_tf32(c[nt][3] * r1);
    }

    unsigned a[8][4];
    const int src1 = (gid << 2) + (tig >> 1);
    const int src2 = src1 + 2;
    const bool odd = (tig & 1);
#pragma unroll
    for (int kt = 0; kt < 8; kt++) {
        float p0 = __shfl_sync(~0u, c[kt][0], src1);
        float p1 = __shfl_sync(~0u, c[kt][1], src1);
        float p2 = __shfl_sync(~0u, c[kt][2], src1);
        float p3 = __shfl_sync(~0u, c[kt][3], src1);
        float q0 = __shfl_sync(~0u, c[kt][0], src2);
        float q1 = __shfl_sync(~0u, c[kt][1], src2);
        float q2 = __shfl_sync(~0u, c[kt][2], src2);
        float q3 = __shfl_sync(~0u, c[kt][3], src2);
        a[kt][0] = f2u(odd ? p1 : p0);
        a[kt][1] = f2u(odd ? p3 : p2);
        a[kt][2] = f2u(odd ? q1 : q0);
        a[kt][3] = f2u(odd ? q3 : q2);
    }

    float co[4][4];
#pragma unroll
    for (int nt = 0; nt < 4; nt++)
        co[nt][0] = co[nt][1] = co[nt][2] = co[nt][3] = 0.f;

#pragma unroll
    for (int g = 0; g < 4; g++) {
        float4 vb[4];
#pragma unroll
        for (int nt = 0; nt < 4; nt++)
            vb[nt] = *(const float4*)(vg + (8 * nt + gid) * 64 + g * 16 + tig * 4);
        int kt0 = 2 * g;
#pragma unroll
        for (int nt = 0; nt < 4; nt++) {
            mma_tf32(co[nt], a[kt0][0], a[kt0][1], a[kt0][2], a[kt0][3],
                     f2u(vb[nt].x), f2u(vb[nt].y));
            mma_tf32(co[nt], a[kt0 + 1][0], a[kt0 + 1][1], a[kt0 + 1][2], a[kt0 + 1][3],
                     f2u(vb[nt].z), f2u(vb[nt].w));
        }
    }

    // store O into g_o (permuted tf32, A operand of proj GEMM)
    size_t orow0 = ((size_t)(b * 64 + i0)) * CDIM;
    size_t orow1 = ((size_t)(b * 64 + i1)) * CDIM;
#pragma unroll
    for (int nt = 0; nt < 4; nt++) {
        int col = h * 32 + nt * 8 + 2 * tig;     // even
        int p = (col & ~15) | ((col & 3) << 2) | ((col >> 2) & 3);
        g_o[orow0 + p]     = to_tf32(co[nt][0]);
        g_o[orow0 + p + 4] = to_tf32(co[nt][1]);
        g_o[orow1 + p]     = to_tf32(co[nt][2]);
        g_o[orow1 + p + 4] = to_tf32(co[nt][3]);
    }
}

// ---------------- launch ----------------
extern "C" void kernel_launch(void* const* d_in, const int* in_sizes, int n_in,
                              void* d_out, int out_size)
{
    const float* x          = (const float*)d_in[0];
    const float* mask       = (const float*)d_in[1];
    const float* Wq         = (const float*)d_in[2];
    const float* bq         = (const float*)d_in[3];
    const float* Wkv        = (const float*)d_in[4];
    const float* bkv        = (const float*)d_in[5];
    const float* bias_table = (const float*)d_in[6];
    const float* Wp         = (const float*)d_in[7];
    const float* bp         = (const float*)d_in[8];
    float* out = (float*)d_out;

    float* wt;
    cudaGetSymbolAddress((void**)&wt, g_wt);
    float* xt;
    cudaGetSymbolAddress((void**)&xt, g_xt);

    permute_tf32<<<(MROWS * 16 + 255) / 256, 256>>>(x, xt, MROWS * 16);
    permute_tf32<<<(256 * 16 + 255) / 256, 256>>>(Wq, wt, 256 * 16);
    permute_tf32<<<(512 * 16 + 255) / 256, 256>>>(Wkv, wt + 256 * CDIM, 512 * 16);
    permute_tf32<<<(256 * 16 + 255) / 256, 256>>>(Wp, wt + 768 * CDIM, 256 * 16);
    bias8_kernel<<<128, 256>>>(bias_table);

    mma_gemm<0><<<dim3(6, MROWS / 128), 256>>>(bq, bkv, nullptr);
    attn_kernel<<<BWIN * HEADS, 128>>>(mask);
    mma_gemm<1><<<dim3(2, MROWS / 128), 256>>>(bp, nullptr, out);
}

// round 12
// speedup vs baseline: 1.8992x; 1.2293x over previous
#include <cuda_runtime.h>
#include <cstddef>
#include <cstdint>

// ---------------- problem constants ----------------
constexpr int BWIN = 4096;
constexpr int NTOK = 64;
constexpr int CDIM = 256;
constexpr int HEADS = 8;
constexpr int MROWS = BWIN * NTOK;          // 262144
constexpr float SCALE = 0.1767766952966369f; // 32^-0.5

// ---------------- scratch ----------------
// q/k: [bh][n][32] k-permuted tf32.  v: [bh][d][64] n-permuted tf32 (transposed).
__device__ float g_q[BWIN * HEADS * NTOK * 32];
__device__ float g_k[BWIN * HEADS * NTOK * 32];
__device__ float g_v[BWIN * HEADS * NTOK * 32];
__device__ float g_o[MROWS * CDIM];         // tf32-rounded fp32 [m][256]
__device__ float g_wt[1024 * CDIM];         // RNA-rounded weights: [0,256)=Wq,[256,768)=Wkv,[768,1024)=Wp
__device__ float g_bias8[HEADS * 64 * 64];

// ---------------- helpers ----------------
__device__ __forceinline__ float to_tf32(float x) {
    unsigned r;
    asm("cvt.rna.tf32.f32 %0, %1;" : "=r"(r) : "f"(x));
    return __uint_as_float(r);
}
__device__ __forceinline__ unsigned f2u(float x) { return __float_as_uint(x); }
// HMMA ignores low 13 mantissa bits (RZ). Adding 0x1000 before the MMA
// implements round-to-nearest (rna) of the tf32 operand.
__device__ __forceinline__ unsigned rna(float x) { return __float_as_uint(x) + 0x1000u; }

__device__ __forceinline__ void mma_tf32(float* c, unsigned a0, unsigned a1,
                                         unsigned a2, unsigned a3,
                                         unsigned b0, unsigned b1) {
    asm volatile(
        "mma.sync.aligned.m16n8k8.row.col.f32.tf32.tf32.f32 "
        "{%0,%1,%2,%3}, {%4,%5,%6,%7}, {%8,%9}, {%0,%1,%2,%3};"
        : "+f"(c[0]), "+f"(c[1]), "+f"(c[2]), "+f"(c[3])
        : "r"(a0), "r"(a1), "r"(a2), "r"(a3), "r"(b0), "r"(b1));
}

__device__ __forceinline__ void cp16(uint32_t dst, const void* src) {
    asm volatile("cp.async.cg.shared.global [%0], [%1], 16;" :: "r"(dst), "l"(src) : "memory");
}
__device__ __forceinline__ void cp_commit() {
    asm volatile("cp.async.commit_group;" ::: "memory");
}
template <int N>
__device__ __forceinline__ void cp_wait() {
    asm volatile("cp.async.wait_group %0;" :: "n"(N) : "memory");
}

// ---------------- round weights (RNA tf32) into g_wt ----------------
__global__ void __launch_bounds__(256) round_w(
    const float* __restrict__ Wq, const float* __restrict__ Wkv,
    const float* __restrict__ Wp)
{
    int fi = blockIdx.x * 256 + threadIdx.x;    // float4 index, 0..65535
    int row = fi >> 6;                          // 0..1023
    int col4 = fi & 63;
    const float* src;
    if (row < 256) src = Wq + ((size_t)row * 64 + col4) * 4;
    else if (row < 768) src = Wkv + ((size_t)(row - 256) * 64 + col4) * 4;
    else src = Wp + ((size_t)(row - 768) * 64 + col4) * 4;
    float4 v = *(const float4*)src;
    float4 r = make_float4(to_tf32(v.x), to_tf32(v.y), to_tf32(v.z), to_tf32(v.w));
    *((float4*)g_wt + fi) = r;
}

// ---------------- expand relative-position bias to [h][i][j] ----------------
__global__ void __launch_bounds__(256) bias8_kernel(const float* __restrict__ bias_table)
{
    int idx = blockIdx.x * 256 + threadIdx.x;
    int h = idx >> 12;
    int ij = idx & 4095;
    int i = ij >> 6, j = ij & 63;
    int ih = i >> 3, iw = i & 7, jh = j >> 3, jw = j & 7;
    int ridx = (ih - jh + 7) * 15 + (iw - jw + 7);
    g_bias8[idx] = bias_table[ridx * 8 + h];
}

// ---------------- TF32 tensor GEMM, cp.async 3-stage, direct fp32 A ----------------
// CTA tile 128x128xK256; 8 warps (4m x 2n), warp tile 32x64.
// A fragments RNA-rounded in registers (+0x1000); W pre-rounded in g_wt.
// MODE 0: A=x; W rows c0..c0+127 of g_wt; scatter -> g_q/g_k/g_v.
// MODE 1: A=g_o (pre-rounded); W rows 768+c0.. -> outP.
template <int MODE>
__global__ void __launch_bounds__(256, 2) mma_gemm(
    const float* __restrict__ A_in,
    const float* __restrict__ b0v, const float* __restrict__ b1v,
    float* __restrict__ outP)
{
    constexpr int STAGES = 3;
    __shared__ float4 As4[STAGES][128 * 4];
    __shared__ float4 Bs4[STAGES][128 * 4];

    const float* A = (MODE == 0) ? A_in : g_o;
    const int c0 = blockIdx.x * 128;
    const int m0 = blockIdx.y * 128;
    const float* Wsrc = g_wt + (size_t)((MODE == 0 ? 0 : 768) + c0) * CDIM;

    const int t = threadIdx.x;
    const int wid = t >> 5, lane = t & 31;
    const int wm = wid & 3, wn = wid >> 2;
    const int gid = lane >> 2, tig = lane & 3;
    const int mrow = wm * 32, ncol = wn * 64;

    float c[2][8][4];
#pragma unroll
    for (int mt = 0; mt < 2; mt++)
#pragma unroll
        for (int nt = 0; nt < 8; nt++)
#pragma unroll
            for (int i = 0; i < 4; i++) c[mt][nt][i] = 0.f;

    // ---- cp.async mapping ----
    const int arow = t >> 2;
    const int ac = t & 3;
    const int apc  = ac ^ ((arow >> 1) & 3);
    const int arowB = arow + 64;
    const int apcB = ac ^ ((arowB >> 1) & 3);

    const uint32_t dA0 = (uint32_t)__cvta_generic_to_shared(&As4[0][arow * 4 + apc]);
    const uint32_t dA1 = (uint32_t)__cvta_generic_to_shared(&As4[0][arowB * 4 + apcB]);
    const uint32_t dB0 = (uint32_t)__cvta_generic_to_shared(&Bs4[0][arow * 4 + apc]);
    const uint32_t dB1 = (uint32_t)__cvta_generic_to_shared(&Bs4[0][arowB * 4 + apcB]);
    constexpr uint32_t STRIDE = 128 * 4 * 16;   // 8 KB per stage

    const float* srcA0 = A + (size_t)(m0 + arow) * CDIM + ac * 4;
    const float* srcA1 = A + (size_t)(m0 + arow + 64) * CDIM + ac * 4;
    const float* srcB0 = Wsrc + (size_t)arow * CDIM + ac * 4;
    const float* srcB1 = Wsrc + (size_t)(arow + 64) * CDIM + ac * 4;

    auto issue = [&](int kt, int s) {
        cp16(dA0 + s * STRIDE, srcA0 + kt * 16);
        cp16(dA1 + s * STRIDE, srcA1 + kt * 16);
        cp16(dB0 + s * STRIDE, srcB0 + kt * 16);
        cp16(dB1 + s * STRIDE, srcB1 + kt * 16);
        cp_commit();
    };

    // ---- fragment load indices (float4 units) ----
    int aIdx[2][2], bIdx[8];
#pragma unroll
    for (int mt = 0; mt < 2; mt++) {
        int r0 = mrow + mt * 16 + gid;
        int r1 = r0 + 8;
        aIdx[mt][0] = r0 * 4 + (tig ^ ((r0 >> 1) & 3));
        aIdx[mt][1] = r1 * 4 + (tig ^ ((r1 >> 1) & 3));
    }
#pragma unroll
    for (int nt = 0; nt < 8; nt++) {
        int nb = ncol + nt * 8 + gid;
        bIdx[nt] = nb * 4 + (tig ^ ((nb >> 1) & 3));
    }

    issue(0, 0);
    issue(1, 1);

#pragma unroll
    for (int kt = 0; kt < 16; kt++) {
        const int buf = kt % 3;
        cp_wait<1>();
        __syncthreads();

        {
            const float4* as = As4[buf];
            const float4* bs = Bs4[buf];
            unsigned au[2][2][4];
#pragma unroll
            for (int mt = 0; mt < 2; mt++) {
#pragma unroll
                for (int half = 0; half < 2; half++) {
                    float4 v = as[aIdx[mt][half]];
                    au[mt][half][0] = rna(v.x);
                    au[mt][half][1] = rna(v.y);
                    au[mt][half][2] = rna(v.z);
                    au[mt][half][3] = rna(v.w);
                }
            }
#pragma unroll
            for (int half = 0; half < 2; half++) {
                float4 b4[4];
#pragma unroll
                for (int j = 0; j < 4; j++) b4[j] = bs[bIdx[half * 4 + j]];
#pragma unroll
                for (int mt = 0; mt < 2; mt++)
#pragma unroll
                    for (int j = 0; j < 4; j++) {
                        float* cc = c[mt][half * 4 + j];
                        mma_tf32(cc,
                                 au[mt][0][0], au[mt][1][0],
                                 au[mt][0][1], au[mt][1][1],
                                 f2u(b4[j].x), f2u(b4[j].y));
                        mma_tf32(cc,
                                 au[mt][0][2], au[mt][1][2],
                                 au[mt][0][3], au[mt][1][3],
                                 f2u(b4[j].z), f2u(b4[j].w));
                    }
            }
        }
        __syncthreads();
        if (kt + 2 < 16) issue(kt + 2, (kt + 2) % 3);
    }

    // ---------------- epilogue ----------------
#pragma unroll
    for (int mt = 0; mt < 2; mt++) {
#pragma unroll
        for (int nt = 0; nt < 8; nt++) {
            int clocal = ncol + nt * 8 + 2 * tig;
            int cg = c0 + clocal;
            float bias0, bias1;
            if (MODE == 1) { bias0 = b0v[cg]; bias1 = b0v[cg + 1]; }
            else if (cg < 256) { bias0 = b0v[cg]; bias1 = b0v[cg + 1]; }
            else { bias0 = b1v[cg - 256]; bias1 = b1v[cg - 255]; }
#pragma unroll
            for (int rr = 0; rr < 2; rr++) {
                int row = m0 + mrow + mt * 16 + gid + rr * 8;
                float v0 = c[mt][nt][rr * 2 + 0] + bias0;
                float v1 = c[mt][nt][rr * 2 + 1] + bias1;
                if (MODE == 1) {
                    float2* p = (float2*)(outP + (size_t)row * CDIM + cg);
                    *p = make_float2(v0, v1);
                } else {
                    int cc = cg;
                    int b = row >> 6, n = row & 63;
                    if (cc < 512) {
                        float* base;
                        if (cc < 256) { base = g_q; v0 *= SCALE; v1 *= SCALE; }
                        else { base = g_k; cc -= 256; }
                        int hh = cc >> 5, dd = cc & 31;
                        int pp = (dd & 16) + ((dd & 3) << 2) + ((dd >> 2) & 3);
                        float* p = base + ((size_t)(b * 8 + hh)) * 2048 + n * 32;
                        p[pp] = to_tf32(v0);
                        p[pp + 4] = to_tf32(v1);
                    } else {
                        cc -= 512;
                        int hh = cc >> 5, dd = cc & 31;
                        int pn = (n & ~15) + ((n & 3) << 2) + ((n >> 2) & 3);
                        float* p = g_v + ((size_t)(b * 8 + hh)) * 2048 + dd * 64 + pn;
                        p[0] = to_tf32(v0);
                        p[64] = to_tf32(v1);
                    }
                }
            }
        }
    }
}

// ---------------- tensor-core attention per (window, head) ----------------
__global__ void __launch_bounds__(128) attn_kernel(const float* __restrict__ mask)
{
    const int bh = blockIdx.x;
    const int b  = bh >> 3;
    const int h  = bh & 7;
    const int w  = b & 1023;

    const int t = threadIdx.x;
    const int wid = t >> 5, lane = t & 31;
    const int gid = lane >> 2, tig = lane & 3;
    const int i0 = wid * 16 + gid;
    const int i1 = i0 + 8;

    const float* qg = g_q + (size_t)bh * 2048;
    const float* kg = g_k + (size_t)bh * 2048;
    const float* vg = g_v + (size_t)bh * 2048;

    float4 qa00 = *(const float4*)(qg + i0 * 32 + tig * 4);
    float4 qa01 = *(const float4*)(qg + i0 * 32 + 16 + tig * 4);
    float4 qa10 = *(const float4*)(qg + i1 * 32 + tig * 4);
    float4 qa11 = *(const float4*)(qg + i1 * 32 + 16 + tig * 4);

    float c[8][4];
#pragma unroll
    for (int nt = 0; nt < 8; nt++) {
        c[nt][0] = c[nt][1] = c[nt][2] = c[nt][3] = 0.f;
        const float* krow = kg + (8 * nt + gid) * 32;
        float4 kb0 = *(const float4*)(krow + tig * 4);
        float4 kb1 = *(const float4*)(krow + 16 + tig * 4);
        mma_tf32(c[nt], f2u(qa00.x), f2u(qa10.x), f2u(qa00.y), f2u(qa10.y), f2u(kb0.x), f2u(kb0.y));
        mma_tf32(c[nt], f2u(qa00.z), f2u(qa10.z), f2u(qa00.w), f2u(qa10.w), f2u(kb0.z), f2u(kb0.w));
        mma_tf32(c[nt], f2u(qa01.x), f2u(qa11.x), f2u(qa01.y), f2u(qa11.y), f2u(kb1.x), f2u(kb1.y));
        mma_tf32(c[nt], f2u(qa01.z), f2u(qa11.z), f2u(qa01.w), f2u(qa11.w), f2u(kb1.z), f2u(kb1.w));
    }

    const float* mrow = mask + (size_t)w * 4096;
    const float* brow = g_bias8 + h * 4096;
    float mx0 = -1e30f, mx1 = -1e30f;
#pragma unroll
    for (int nt = 0; nt < 8; nt++) {
        int coff = nt * 8 + 2 * tig;
        float2 m0 = *(const float2*)(mrow + i0 * 64 + coff);
        float2 b0 = *(const float2*)(brow + i0 * 64 + coff);
        float2 m1 = *(const float2*)(mrow + i1 * 64 + coff);
        float2 b1 = *(const float2*)(brow + i1 * 64 + coff);
        c[nt][0] += m0.x + b0.x;
        c[nt][1] += m0.y + b0.y;
        c[nt][2] += m1.x + b1.x;
        c[nt][3] += m1.y + b1.y;
        mx0 = fmaxf(mx0, fmaxf(c[nt][0], c[nt][1]));
        mx1 = fmaxf(mx1, fmaxf(c[nt][2], c[nt][3]));
    }
    mx0 = fmaxf(mx0, __shfl_xor_sync(~0u, mx0, 1));
    mx0 = fmaxf(mx0, __shfl_xor_sync(~0u, mx0, 2));
    mx1 = fmaxf(mx1, __shfl_xor_sync(~0u, mx1, 1));
    mx1 = fmaxf(mx1, __shfl_xor_sync(~0u, mx1, 2));

    float s0 = 0.f, s1 = 0.f;
#pragma unroll
    for (int nt = 0; nt < 8; nt++) {
        c[nt][0] = __expf(c[nt][0] - mx0);
        c[nt][1] = __expf(c[nt][1] - mx0);
        c[nt][2] = __expf(c[nt][2] - mx1);
        c[nt][3] = __expf(c[nt][3] - mx1);
        s0 += c[nt][0] + c[nt][1];
        s1 += c[nt][2] + c[nt][3];
    }
    s0 += __shfl_xor_sync(~0u, s0, 1);
    s0 += __shfl_xor_sync(~0u, s0, 2);
    s1 += __shfl_xor_sync(~0u, s1, 1);
    s1 += __shfl_xor_sync(~0u, s1, 2);
    float r0 = 1.0f / s0, r1 = 1.0f / s1;
#pragma unroll
    for (int nt = 0; nt < 8; nt++) {
        c[nt][0] = to_tf32(c[nt][0] * r0);
        c[nt][1] = to_tf32(c[nt][1] * r0);
        c[nt][2] = to_tf32(c[nt][2] * r1);
        c[nt][3] = to_tf32(c[nt][3] * r1);
    }

    unsigned a[8][4];
    const int src1 = (gid << 2) + (tig >> 1);
    const int src2 = src1 + 2;
    const bool odd = (tig & 1);
#pragma unroll
    for (int kt = 0; kt < 8; kt++) {
        float p0 = __shfl_sync(~0u, c[kt][0], src1);
        float p1 = __shfl_sync(~0u, c[kt][1], src1);
        float p2 = __shfl_sync(~0u, c[kt][2], src1);
        float p3 = __shfl_sync(~0u, c[kt][3], src1);
        float q0 = __shfl_sync(~0u, c[kt][0], src2);
        float q1 = __shfl_sync(~0u, c[kt][1], src2);
        float q2 = __shfl_sync(~0u, c[kt][2], src2);
        float q3 = __shfl_sync(~0u, c[kt][3], src2);
        a[kt][0] = f2u(odd ? p1 : p0);
        a[kt][1] = f2u(odd ? p3 : p2);
        a[kt][2] = f2u(odd ? q1 : q0);
        a[kt][3] = f2u(odd ? q3 : q2);
    }

    float co[4][4];
#pragma unroll
    for (int nt = 0; nt < 4; nt++)
        co[nt][0] = co[nt][1] = co[nt][2] = co[nt][3] = 0.f;

#pragma unroll
    for (int g = 0; g < 4; g++) {
        float4 vb[4];
#pragma unroll
        for (int nt = 0; nt < 4; nt++)
            vb[nt] = *(const float4*)(vg + (8 * nt + gid) * 64 + g * 16 + tig * 4);
        int kt0 = 2 * g;
#pragma unroll
        for (int nt = 0; nt < 4; nt++) {
            mma_tf32(co[nt], a[kt0][0], a[kt0][1], a[kt0][2], a[kt0][3],
                     f2u(vb[nt].x), f2u(vb[nt].y));
            mma_tf32(co[nt], a[kt0 + 1][0], a[kt0 + 1][1], a[kt0 + 1][2], a[kt0 + 1][3],
                     f2u(vb[nt].z), f2u(vb[nt].w));
        }
    }

    // store O tf32-rounded: g_o[m][h*32 + d] (A operand of proj GEMM)
    size_t orow0 = ((size_t)(b * 64 + i0)) * CDIM + h * 32;
    size_t orow1 = ((size_t)(b * 64 + i1)) * CDIM + h * 32;
#pragma unroll
    for (int nt = 0; nt < 4; nt++) {
        int col = nt * 8 + 2 * tig;
        *(float2*)&g_o[orow0 + col] = make_float2(to_tf32(co[nt][0]), to_tf32(co[nt][1]));
        *(float2*)&g_o[orow1 + col] = make_float2(to_tf32(co[nt][2]), to_tf32(co[nt][3]));
    }
}

// ---------------- launch ----------------
extern "C" void kernel_launch(void* const* d_in, const int* in_sizes, int n_in,
                              void* d_out, int out_size)
{
    const float* x          = (const float*)d_in[0];
    const float* mask       = (const float*)d_in[1];
    const float* Wq         = (const float*)d_in[2];
    const float* bq         = (const float*)d_in[3];
    const float* Wkv        = (const float*)d_in[4];
    const float* bkv        = (const float*)d_in[5];
    const float* bias_table = (const float*)d_in[6];
    const float* Wp         = (const float*)d_in[7];
    const float* bp         = (const float*)d_in[8];
    float* out = (float*)d_out;

    round_w<<<256, 256>>>(Wq, Wkv, Wp);
    bias8_kernel<<<128, 256>>>(bias_table);
    mma_gemm<0><<<dim3(6, MROWS / 128), 256>>>(x, bq, bkv, nullptr);
    attn_kernel<<<BWIN * HEADS, 128>>>(mask);
    mma_gemm<1><<<dim3(2, MROWS / 128), 256>>>(nullptr, bp, nullptr, out);
}